// round 17
// baseline (speedup 1.0000x reference)
#include <cuda_runtime.h>
#include <cuda_fp16.h>
#include <math.h>
#include <stdint.h>

#define D 128
#define DD 16384
#define BATCH 16
#define NSEQ 1024
#define M_ROWS 16384
#define NE 32768
#define NS 6
#define NL 4

typedef unsigned long long u64;
typedef unsigned int u32;
typedef long long i64;
typedef __half f16;

// ---------------- scratch -------------------------------------------------------
__device__ __align__(256) float g_T [M_ROWS * D];
__device__ __align__(256) f16 s_ctrs_h[M_ROWS*D];
__device__ __align__(256) f16 s_feat_h[M_ROWS*D];
__device__ __align__(256) f16 s_q_h[M_ROWS*D];
__device__ __align__(256) f16 s_k_h[M_ROWS*D];
__device__ __align__(256) f16 s_vt_h[M_ROWS*D];
__device__ __align__(256) f16 s_x_h[M_ROWS*D];
__device__ __align__(256) f16 s_sc_h[(size_t)BATCH*NSEQ*NSEQ];
__device__ __align__(256) f16 s_wq_h[DD], s_wk_h[DD], s_wv_h[DD];
__device__ __align__(256) f16 s_wc_h[NL*DD];
__device__ __align__(256) f16 s_wp_h[NL*NS*DD];
__device__ __align__(256) f16 s_ws_h[NL*NS*DD];
__device__ __align__(256) f16 s_wl_h[NL*DD];
__device__ __align__(256) f16 s_wr_h[NL*DD];
__device__ __align__(256) f16 s_w2_h[NL*DD];

// ---------------- PTX helpers ------------------------------------------------
__device__ __forceinline__ u32 smem_u32(const void* p) {
    u32 a;
    asm("{ .reg .u64 t; cvta.to.shared.u64 t, %1; cvt.u32.u64 %0, t; }" : "=r"(a) : "l"(p));
    return a;
}
__device__ __forceinline__ void ldsm4(u32* r, u32 addr) {
    asm volatile("ldmatrix.sync.aligned.m8n8.x4.shared.b16 {%0,%1,%2,%3}, [%4];"
                 : "=r"(r[0]), "=r"(r[1]), "=r"(r[2]), "=r"(r[3]) : "r"(addr));
}
__device__ __forceinline__ void mma_f16(float* d, const u32* a, u32 b0, u32 b1) {
    asm volatile("mma.sync.aligned.m16n8k16.row.col.f32.f16.f16.f32 "
                 "{%0,%1,%2,%3}, {%4,%5,%6,%7}, {%8,%9}, {%0,%1,%2,%3};"
                 : "+f"(d[0]), "+f"(d[1]), "+f"(d[2]), "+f"(d[3])
                 : "r"(a[0]), "r"(a[1]), "r"(a[2]), "r"(a[3]), "r"(b0), "r"(b1));
}
__device__ __forceinline__ void red4(float* p, float a, float b, float c, float d) {
    asm volatile("red.global.add.v4.f32 [%0], {%1,%2,%3,%4};"
                 :: "l"(p), "f"(a), "f"(b), "f"(c), "f"(d) : "memory");
}
__device__ __forceinline__ void cp16_cg(u32 dst, const void* src) {
    asm volatile("cp.async.cg.shared.global [%0], [%1], 16;" :: "r"(dst), "l"(src));
}
__device__ __forceinline__ void cp16_ca(u32 dst, const void* src) {
    asm volatile("cp.async.ca.shared.global [%0], [%1], 16;" :: "r"(dst), "l"(src));
}
__device__ __forceinline__ void cp_commit() { asm volatile("cp.async.commit_group;" ::: "memory"); }
template<int N> __device__ __forceinline__ void cp_wait() {
    asm volatile("cp.async.wait_group %0;" :: "n"(N) : "memory");
}
__device__ __forceinline__ uint2 cvt4(float4 v) {
    __half2 h0 = __floats2half2_rn(v.x, v.y);
    __half2 h1 = __floats2half2_rn(v.z, v.w);
    return make_uint2(*(u32*)&h0, *(u32*)&h1);
}

// =====================================================================
// MMA fragment compute over one resident 128-K tile pair (two halves).
// =====================================================================
__device__ __forceinline__ void compute_tile(
    float acc[2][8][4], u32 abase0, u32 bbase0, int a_hi, int b_hi, int xr)
{
    #pragma unroll
    for (int h = 0; h < 2; h++) {
        const u32 abase = abase0 + (u32)h * 16384u;
        const u32 bbase = bbase0 + (u32)h * 16384u;
        #pragma unroll
        for (int ks = 0; ks < 4; ks++) {
            const u32 aoff = (u32)(((ks * 2 + a_hi) ^ xr) << 4);
            const u32 boff = (u32)(((ks * 2 + b_hi) ^ xr) << 4);
            u32 b[4][4], a0[4], a1[4];
            #pragma unroll
            for (int p = 0; p < 4; p++)
                ldsm4(b[p], bbase + boff + p * 2048);
            ldsm4(a0, abase + aoff);
            ldsm4(a1, abase + aoff + 2048);
            #pragma unroll
            for (int nj = 0; nj < 8; nj++) {
                u32 bb0 = b[nj >> 1][(nj & 1) * 2], bb1 = b[nj >> 1][(nj & 1) * 2 + 1];
                mma_f16(acc[0][nj], a0, bb0, bb1);
                mma_f16(acc[1][nj], a1, bb0, bb1);
            }
        }
    }
}

// ---------------- fused gn1 + ctr2 GEMM + gn2 kernel -----------------------------
__global__ __launch_bounds__(256, 2)
void gemm_gn12_k(float* __restrict__ T,
                 const f16* __restrict__ Bh,
                 float* __restrict__ X, f16* __restrict__ Ch,
                 const float* __restrict__ g1w, const float* __restrict__ b1w,
                 const float* __restrict__ g2w, const float* __restrict__ b2w)
{
    extern __shared__ char sm[];
    const u32 sb = smem_u32(sm);
    const int row0 = blockIdx.x * 128;
    const int tid = threadIdx.x;
    const int wid = tid >> 5, lane = tid & 31;
    const int m0w = (wid >> 1) * 32, n0w = (wid & 1) * 64;
    const int r_ld = tid >> 1;
    const int hh_ld = tid & 1;

    {
        const f16* bp = Bh + (i64)r_ld * D;
        #pragma unroll
        for (int h = 0; h < 2; h++)
            #pragma unroll
            for (int j = 0; j < 4; j++) {
                int c = hh_ld * 4 + j;
                u32 so = (u32)r_ld * 128 + (u32)((c ^ (r_ld & 7)) << 4);
                cp16_ca(sb + 32768u + (u32)h * 16384u + so, bp + h * 64 + c * 8);
            }
        cp_commit();
    }

    // T rows -> GN1 + relu -> fp16 A smem; zero T in place
    {
        float* Tp = T + (i64)(row0 + r_ld) * D + hh_ld * 64;
        float4 tv[16];
        float s1 = 0.f, s2 = 0.f;
        #pragma unroll
        for (int j = 0; j < 16; j++) {
            tv[j] = *reinterpret_cast<const float4*>(Tp + j * 4);
            s1 += tv[j].x + tv[j].y + tv[j].z + tv[j].w;
            s2 += tv[j].x * tv[j].x + tv[j].y * tv[j].y + tv[j].z * tv[j].z + tv[j].w * tv[j].w;
        }
        s1 += __shfl_xor_sync(0xffffffffu, s1, 1);
        s2 += __shfl_xor_sync(0xffffffffu, s2, 1);
        const float mu = s1 * (1.f / 128.f);
        const float var = s2 * (1.f / 128.f) - mu * mu;
        const float rstd = rsqrtf(var + 1e-5f);
        const float* gp = g1w + hh_ld * 64;
        const float* bp = b1w + hh_ld * 64;
        #pragma unroll
        for (int j = 0; j < 16; j++) {
            float4 g4 = *reinterpret_cast<const float4*>(gp + j * 4);
            float4 b4 = *reinterpret_cast<const float4*>(bp + j * 4);
            float4 y;
            y.x = fmaxf((tv[j].x - mu) * rstd * g4.x + b4.x, 0.f);
            y.y = fmaxf((tv[j].y - mu) * rstd * g4.y + b4.y, 0.f);
            y.z = fmaxf((tv[j].z - mu) * rstd * g4.z + b4.z, 0.f);
            y.w = fmaxf((tv[j].w - mu) * rstd * g4.w + b4.w, 0.f);
            int c = j >> 1;
            u32 so = (u32)r_ld * 128 + (u32)((c ^ (r_ld & 7)) << 4) + (u32)(j & 1) * 8;
            *reinterpret_cast<uint2*>(sm + hh_ld * 16384 + so) = cvt4(y);
            *reinterpret_cast<float4*>(Tp + j * 4) = make_float4(0.f, 0.f, 0.f, 0.f);
        }
    }
    cp_wait<0>();
    __syncthreads();

    float acc[2][8][4];
    #pragma unroll
    for (int mi = 0; mi < 2; mi++)
        #pragma unroll
        for (int nj = 0; nj < 8; nj++)
            #pragma unroll
            for (int e = 0; e < 4; e++) acc[mi][nj][e] = 0.f;

    const u32 a_rb = (u32)(m0w + (lane & 15)) * 128;
    const u32 b_rb = (u32)(n0w + ((lane >> 4) << 3) + (lane & 7)) * 128;
    const int a_hi = lane >> 4;
    const int b_hi = (lane >> 3) & 1;
    const int xr = lane & 7;
    compute_tile(acc, sb + a_rb, sb + 32768u + b_rb, a_hi, b_hi, xr);
    __syncthreads();

    float* Cs = reinterpret_cast<float*>(sm);
    const int g = lane >> 2, q2 = (lane & 3) * 2;
    #pragma unroll
    for (int mi = 0; mi < 2; mi++)
        #pragma unroll
        for (int nj = 0; nj < 8; nj++) {
            int r = m0w + mi * 16 + g;
            int c = n0w + nj * 8 + q2;
            Cs[r * 132 + c]           = acc[mi][nj][0];
            Cs[r * 132 + c + 1]       = acc[mi][nj][1];
            Cs[(r + 8) * 132 + c]     = acc[mi][nj][2];
            Cs[(r + 8) * 132 + c + 1] = acc[mi][nj][3];
        }
    __syncthreads();

    const int rr = tid >> 1, hh = tid & 1;
    const float* srow = Cs + rr * 132 + hh * 64;
    float s1 = 0.f, s2 = 0.f;
    #pragma unroll
    for (int j = 0; j < 16; j++) {
        float4 vv = *reinterpret_cast<const float4*>(srow + j * 4);
        s1 += vv.x + vv.y + vv.z + vv.w;
        s2 += vv.x * vv.x + vv.y * vv.y + vv.z * vv.z + vv.w * vv.w;
    }
    s1 += __shfl_xor_sync(0xffffffffu, s1, 1);
    s2 += __shfl_xor_sync(0xffffffffu, s2, 1);
    const float mu = s1 * (1.f / 128.f);
    const float var = s2 * (1.f / 128.f) - mu * mu;
    const float rstd = rsqrtf(var + 1e-5f);
    const i64 ro = (i64)(row0 + rr) * D + hh * 64;
    float* p = X + ro;
    const float* gp = g2w + hh * 64;
    const float* bp = b2w + hh * 64;
    #pragma unroll
    for (int j = 0; j < 16; j++) {
        float4 vv = *reinterpret_cast<const float4*>(srow + j * 4);
        float4 g4 = *reinterpret_cast<const float4*>(gp + j * 4);
        float4 b4 = *reinterpret_cast<const float4*>(bp + j * 4);
        float4 f4 = *reinterpret_cast<const float4*>(p + j * 4);
        vv.x = fmaxf((vv.x - mu) * rstd * g4.x + b4.x + f4.x, 0.f);
        vv.y = fmaxf((vv.y - mu) * rstd * g4.y + b4.y + f4.y, 0.f);
        vv.z = fmaxf((vv.z - mu) * rstd * g4.z + b4.z + f4.z, 0.f);
        vv.w = fmaxf((vv.w - mu) * rstd * g4.w + b4.w + f4.w, 0.f);
        *reinterpret_cast<float4*>(p + j * 4) = vv;
        *reinterpret_cast<uint2*>(Ch + ro + j * 4) = cvt4(vv);
    }
}

// ---------------- fused QKV kernel (z=0:Q, z=1:K, z=2:V->transposed) ------------
__global__ __launch_bounds__(256, 2)
void qkv_k(const f16* __restrict__ ctrs_h, const f16* __restrict__ feat_h,
           const f16* __restrict__ wq, const f16* __restrict__ wk, const f16* __restrict__ wv,
           f16* __restrict__ q_h, f16* __restrict__ k_h, f16* __restrict__ vt_h)
{
    extern __shared__ char sm[];
    const u32 sb = smem_u32(sm);
    const int z = blockIdx.z;
    const int row0 = blockIdx.x * 128;
    const f16* Ah = (z == 0) ? ctrs_h : feat_h;
    const f16* Bh = (z == 0) ? wq : (z == 1) ? wk : wv;

    const int tid = threadIdx.x;
    const int wid = tid >> 5, lane = tid & 31;
    const int m0w = (wid >> 1) * 32, n0w = (wid & 1) * 64;

    float acc[2][8][4];
    #pragma unroll
    for (int mi = 0; mi < 2; mi++)
        #pragma unroll
        for (int nj = 0; nj < 8; nj++)
            #pragma unroll
            for (int e = 0; e < 4; e++) acc[mi][nj][e] = 0.f;

    const u32 a_rb = (u32)(m0w + (lane & 15)) * 128;
    const u32 b_rb = (u32)(n0w + ((lane >> 4) << 3) + (lane & 7)) * 128;
    const int a_hi = lane >> 4;
    const int b_hi = (lane >> 3) & 1;
    const int xr = lane & 7;
    const int r_ld = tid >> 1;
    const int c0_ld = (tid & 1) * 4;

    {
        const f16* ap = Ah + (i64)(row0 + r_ld) * D;
        const f16* bp = Bh + (i64)r_ld * D;
        #pragma unroll
        for (int h = 0; h < 2; h++)
            #pragma unroll
            for (int j = 0; j < 4; j++) {
                int c = c0_ld + j;
                u32 so = (u32)r_ld * 128 + (u32)((c ^ (r_ld & 7)) << 4);
                cp16_cg(sb + (u32)h * 16384u + so,          ap + h * 64 + c * 8);
                cp16_ca(sb + 32768u + (u32)h * 16384u + so, bp + h * 64 + c * 8);
            }
        cp_commit();
    }
    cp_wait<0>();
    __syncthreads();
    compute_tile(acc, sb + a_rb, sb + 32768u + b_rb, a_hi, b_hi, xr);
    __syncthreads();

    float* Cs = reinterpret_cast<float*>(sm);
    const int g = lane >> 2, q2 = (lane & 3) * 2;
    #pragma unroll
    for (int mi = 0; mi < 2; mi++)
        #pragma unroll
        for (int nj = 0; nj < 8; nj++) {
            int r = m0w + mi * 16 + g;
            int c = n0w + nj * 8 + q2;
            Cs[r * 132 + c]           = acc[mi][nj][0];
            Cs[r * 132 + c + 1]       = acc[mi][nj][1];
            Cs[(r + 8) * 132 + c]     = acc[mi][nj][2];
            Cs[(r + 8) * 132 + c + 1] = acc[mi][nj][3];
        }
    __syncthreads();

    if (z < 2) {
        f16* out = (z == 0) ? q_h : k_h;
        const int rr = tid >> 1, hh = tid & 1;
        const float* srow = Cs + rr * 132 + hh * 64;
        const i64 ro = (i64)(row0 + rr) * D + hh * 64;
        #pragma unroll
        for (int j = 0; j < 16; j++) {
            float4 vv = *reinterpret_cast<const float4*>(srow + j * 4);
            *reinterpret_cast<uint2*>(out + ro + j * 4) = cvt4(vv);
        }
    } else {
        const int d = tid >> 1, hh = tid & 1;
        const int jg0 = row0 + hh * 64;
        const int b = jg0 >> 10, jin = jg0 & 1023;
        f16* dst = vt_h + (i64)b * D * NSEQ + (i64)d * NSEQ + jin;
        #pragma unroll
        for (int j = 0; j < 64; j += 2) {
            float a0 = Cs[(hh * 64 + j) * 132 + d];
            float a1 = Cs[(hh * 64 + j + 1) * 132 + d];
            __half2 hv = __floats2half2_rn(a0, a1);
            *reinterpret_cast<u32*>(dst + j) = *(u32*)&hv;
        }
    }
}

// ---------------- QK scores kernel: A-resident, 4 B tiles streamed, fp16 out -----
__global__ __launch_bounds__(256, 2)
void qk_k(const f16* __restrict__ q_h, const f16* __restrict__ k_h,
          f16* __restrict__ sch, float scale)
{
    extern __shared__ char sm[];
    const u32 sb = smem_u32(sm);
    const int z = blockIdx.z;
    const int row0 = blockIdx.x * 128;
    const int cg0 = blockIdx.y * 4;
    const f16* Ab = q_h + (i64)z * NSEQ * D;
    const f16* Bb = k_h + (i64)z * NSEQ * D;
    f16* Cb = sch + (i64)z * NSEQ * NSEQ;

    const int tid = threadIdx.x;
    const int wid = tid >> 5, lane = tid & 31;
    const int m0w = (wid >> 1) * 32, n0w = (wid & 1) * 64;
    const u32 a_rb = (u32)(m0w + (lane & 15)) * 128;
    const u32 b_rb = (u32)(n0w + ((lane >> 4) << 3) + (lane & 7)) * 128;
    const int a_hi = lane >> 4;
    const int b_hi = (lane >> 3) & 1;
    const int xr = lane & 7;
    const int r_ld = tid >> 1;
    const int c0_ld = (tid & 1) * 4;

    {
        const f16* ap = Ab + (i64)(row0 + r_ld) * D;
        #pragma unroll
        for (int h = 0; h < 2; h++)
            #pragma unroll
            for (int j = 0; j < 4; j++) {
                int c = c0_ld + j;
                u32 so = (u32)r_ld * 128 + (u32)((c ^ (r_ld & 7)) << 4);
                cp16_cg(sb + (u32)h * 16384u + so, ap + h * 64 + c * 8);
            }
        cp_commit();
    }
    auto load_B = [&](int ct, int s) {
        const f16* bp = Bb + (i64)(ct * 128 + r_ld) * D;
        const u32 base = sb + 32768u + (u32)s * 32768u;
        #pragma unroll
        for (int h = 0; h < 2; h++)
            #pragma unroll
            for (int j = 0; j < 4; j++) {
                int c = c0_ld + j;
                u32 so = (u32)r_ld * 128 + (u32)((c ^ (r_ld & 7)) << 4);
                cp16_ca(base + (u32)h * 16384u + so, bp + h * 64 + c * 8);
            }
        cp_commit();
    };
    load_B(cg0, 0);

    const int g = lane >> 2;
    const int q = lane & 3;
    const int cb = n0w + ((q >> 1) << 2);
    const bool evenlane = ((lane & 1) == 0);

    for (int i = 0; i < 4; i++) {
        const int s = i & 1;
        if (i < 3) { load_B(cg0 + i + 1, 1 - s); cp_wait<1>(); }
        else       { cp_wait<0>(); }
        __syncthreads();

        float acc[2][8][4];
        #pragma unroll
        for (int mi = 0; mi < 2; mi++)
            #pragma unroll
            for (int nj = 0; nj < 8; nj++)
                #pragma unroll
                for (int e = 0; e < 4; e++) acc[mi][nj][e] = 0.f;

        compute_tile(acc, sb + a_rb, sb + 32768u + (u32)s * 32768u + b_rb, a_hi, b_hi, xr);

        const int col0 = (cg0 + i) * 128;
        #pragma unroll
        for (int mi = 0; mi < 2; mi++) {
            int r1 = row0 + m0w + mi * 16 + g;
            f16* pr = evenlane ? (Cb + (i64)r1 * NSEQ) : (Cb + (i64)(r1 + 8) * NSEQ);
            #pragma unroll
            for (int nj = 0; nj < 8; nj++) {
                float v0 = acc[mi][nj][0] * scale, v1 = acc[mi][nj][1] * scale;
                float v2 = acc[mi][nj][2] * scale, v3 = acc[mi][nj][3] * scale;
                float p0 = __shfl_xor_sync(0xffffffffu, v0, 1);
                float p1 = __shfl_xor_sync(0xffffffffu, v1, 1);
                float p2 = __shfl_xor_sync(0xffffffffu, v2, 1);
                float p3 = __shfl_xor_sync(0xffffffffu, v3, 1);
                float4 o = evenlane ? make_float4(v0, v1, p0, p1)
                                    : make_float4(p2, p3, v2, v3);
                *reinterpret_cast<uint2*>(pr + col0 + cb + nj * 8) = cvt4(o);
            }
        }
        __syncthreads();
    }
}

// ---------------- PV kernel: split-K x2, red.v4 into X (pre-init with feats) -----
__global__ __launch_bounds__(256, 2)
void pv_k(const f16* __restrict__ sc_h, const f16* __restrict__ vt_h,
          float* __restrict__ X)
{
    extern __shared__ char sm[];
    const u32 sb = smem_u32(sm);
    const int z = blockIdx.z;
    const int b = z >> 1, kh = z & 1;
    const int row0 = blockIdx.x * 128;
    const f16* Ab = sc_h + (i64)b * NSEQ * NSEQ + kh * 512;
    const f16* Bb = vt_h + (i64)b * D * NSEQ + kh * 512;
    float* Xb = X + (i64)b * NSEQ * D;

    const int tid = threadIdx.x;
    const int wid = tid >> 5, lane = tid & 31;
    const int m0w = (wid >> 1) * 32, n0w = (wid & 1) * 64;
    const u32 a_rb = (u32)(m0w + (lane & 15)) * 128;
    const u32 b_rb = (u32)(n0w + ((lane >> 4) << 3) + (lane & 7)) * 128;
    const int a_hi = lane >> 4;
    const int b_hi = (lane >> 3) & 1;
    const int xr = lane & 7;
    const int r_ld = tid >> 1;
    const int c0_ld = (tid & 1) * 4;

    float acc[2][8][4];
    #pragma unroll
    for (int mi = 0; mi < 2; mi++)
        #pragma unroll
        for (int nj = 0; nj < 8; nj++)
            #pragma unroll
            for (int e = 0; e < 4; e++) acc[mi][nj][e] = 0.f;

    auto load_half = [&](int h, int s) {
        const int kofs = h * 64;
        const u32 base = sb + (u32)s * 32768u;
        const f16* ap = Ab + (i64)(row0 + r_ld) * NSEQ + kofs;
        const f16* bp = Bb + (i64)r_ld * NSEQ + kofs;
        #pragma unroll
        for (int j = 0; j < 4; j++) {
            int c = c0_ld + j;
            u32 so = (u32)r_ld * 128 + (u32)((c ^ (r_ld & 7)) << 4);
            cp16_cg(base + so,          ap + c * 8);
            cp16_ca(base + 16384u + so, bp + c * 8);
        }
        cp_commit();
    };

    load_half(0, 0);
    for (int h = 0; h < 8; h++) {
        const int s = h & 1;
        if (h < 7) { load_half(h + 1, 1 - s); cp_wait<1>(); }
        else       { cp_wait<0>(); }
        __syncthreads();
        const u32 base = sb + (u32)s * 32768u;
        const u32 abase = base + a_rb;
        const u32 bbase = base + 16384u + b_rb;
        #pragma unroll
        for (int ks = 0; ks < 4; ks++) {
            const u32 aoff = (u32)(((ks * 2 + a_hi) ^ xr) << 4);
            const u32 boff = (u32)(((ks * 2 + b_hi) ^ xr) << 4);
            u32 bf[4][4], a0[4], a1[4];
            #pragma unroll
            for (int p = 0; p < 4; p++)
                ldsm4(bf[p], bbase + boff + p * 2048);
            ldsm4(a0, abase + aoff);
            ldsm4(a1, abase + aoff + 2048);
            #pragma unroll
            for (int nj = 0; nj < 8; nj++) {
                u32 bb0 = bf[nj >> 1][(nj & 1) * 2], bb1 = bf[nj >> 1][(nj & 1) * 2 + 1];
                mma_f16(acc[0][nj], a0, bb0, bb1);
                mma_f16(acc[1][nj], a1, bb0, bb1);
            }
        }
        __syncthreads();
    }

    const int g = lane >> 2;
    const int q = lane & 3;
    const int cb = n0w + ((q >> 1) << 2);
    const bool evenlane = ((lane & 1) == 0);
    #pragma unroll
    for (int mi = 0; mi < 2; mi++) {
        int r1 = row0 + m0w + mi * 16 + g;
        float* pr = evenlane ? (Xb + (i64)r1 * D) : (Xb + (i64)(r1 + 8) * D);
        #pragma unroll
        for (int nj = 0; nj < 8; nj++) {
            float v0 = acc[mi][nj][0], v1 = acc[mi][nj][1];
            float v2 = acc[mi][nj][2], v3 = acc[mi][nj][3];
            float p0 = __shfl_xor_sync(0xffffffffu, v0, 1);
            float p1 = __shfl_xor_sync(0xffffffffu, v1, 1);
            float p2 = __shfl_xor_sync(0xffffffffu, v2, 1);
            float p3 = __shfl_xor_sync(0xffffffffu, v3, 1);
            if (evenlane) red4(pr + cb + nj * 8, v0, v1, p0, p1);
            else          red4(pr + cb + nj * 8, p2, p3, v2, v3);
        }
    }
}

// ---------------- persistent-B scatter kernel (includes ctr group) --------------
// Epilogue reordered AFTER next-tile cp.async issue so red4 drain overlaps loads.
#define NTILES_SC 3840
#define CHUNK_SC 13
#define GRID_SC ((NTILES_SC + CHUNK_SC - 1) / CHUNK_SC)   // 296

__global__ __launch_bounds__(256, 2)
void layer_scatter_p(const f16* __restrict__ Xh,
                     const f16* __restrict__ wch,
                     const f16* __restrict__ wph, const f16* __restrict__ wsh,
                     const f16* __restrict__ wlh, const f16* __restrict__ wrh,
                     float* __restrict__ T,
                     const int* __restrict__ pre_u, const int* __restrict__ pre_v,
                     const int* __restrict__ suc_u, const int* __restrict__ suc_v,
                     const int* __restrict__ left_u, const int* __restrict__ left_v,
                     const int* __restrict__ right_u, const int* __restrict__ right_v)
{
    extern __shared__ char sm[];
    const u32 sb = smem_u32(sm);
    const int t0 = blockIdx.x * CHUNK_SC;
    const int t1 = (t0 + CHUNK_SC < NTILES_SC) ? t0 + CHUNK_SC : NTILES_SC;
    if (t0 >= NTILES_SC) return;

    const int tid = threadIdx.x;
    const int wid = tid >> 5, lane = tid & 31;
    const int m0w = (wid >> 1) * 32, n0w = (wid & 1) * 64;
    const u32 a_rb = (u32)(m0w + (lane & 15)) * 128;
    const u32 b_rb = (u32)(n0w + ((lane >> 4) << 3) + (lane & 7)) * 128;
    const int a_hi = lane >> 4;
    const int b_hi = (lane >> 3) & 1;
    const int xr = lane & 7;
    const int r_ld = tid >> 1;
    const int c0_ld = (tid & 1) * 4;

    auto group_of = [&](int t, const f16*& Bw, const int*& gv, const int*& su, int& base) {
        int g = t >> 8, e = (t & 255) * 128;
        base = e;
        if (g == 0)       { Bw = wch; gv = 0; su = 0; }
        else if (g < 7)   { int z = g - 1; Bw = wph + (i64)z * DD; gv = pre_v + z * NE + e; su = pre_u + z * NE + e; }
        else if (g < 13)  { int z = g - 7; Bw = wsh + (i64)z * DD; gv = suc_v + z * NE + e; su = suc_u + z * NE + e; }
        else if (g == 13) { Bw = wlh; gv = left_v + e; su = left_u + e; }
        else              { Bw = wrh; gv = right_v + e; su = right_u + e; }
    };

    auto load_B = [&](const f16* Bw) {
        const f16* bp = Bw + (i64)r_ld * D;
        #pragma unroll
        for (int h = 0; h < 2; h++) {
            const u32 base = sb + 32768u + (u32)h * 16384u;
            #pragma unroll
            for (int j = 0; j < 4; j++) {
                int c = c0_ld + j;
                u32 so = (u32)r_ld * 128 + (u32)((c ^ (r_ld & 7)) << 4);
                cp16_ca(base + so, bp + h * 64 + c * 8);
            }
        }
        cp_commit();
    };
    auto load_A = [&](const int* gv, int base_row, int h, int s) {
        i64 arow = gv ? (i64)__ldg(gv + r_ld) : (i64)(base_row + r_ld);
        const f16* ap = Xh + arow * D + h * 64;
        const u32 base = sb + (u32)s * 16384u;
        #pragma unroll
        for (int j = 0; j < 4; j++) {
            int c = c0_ld + j;
            u32 so = (u32)r_ld * 128 + (u32)((c ^ (r_ld & 7)) << 4);
            cp16_cg(base + so, ap + c * 8);
        }
        cp_commit();
    };

    const int g = lane >> 2;
    const int q = lane & 3;
    const int cb = n0w + ((q >> 1) << 2);
    const bool evenlane = ((lane & 1) == 0);
    const f16* Bw; const int* gv; const int* su; int base_row;
    group_of(t0, Bw, gv, su, base_row);
    int curg = t0 >> 8;
    load_B(Bw);
    load_A(gv, base_row, 0, 0);
    load_A(gv, base_row, 1, 1);

    for (int t = t0; t < t1; t++) {
        const f16* Bw_n = 0; const int* gv_n = 0; const int* su_n = 0; int base_n = 0;
        const bool have_next = (t + 1 < t1);
        int g_n = curg;
        if (have_next) { group_of(t + 1, Bw_n, gv_n, su_n, base_n); g_n = (t + 1) >> 8; }
        const bool pref0 = have_next && (g_n == curg);

        float acc[2][8][4];
        #pragma unroll
        for (int mi = 0; mi < 2; mi++)
            #pragma unroll
            for (int nj = 0; nj < 8; nj++)
                #pragma unroll
                for (int e = 0; e < 4; e++) acc[mi][nj][e] = 0.f;

        // half 0
        cp_wait<1>(); __syncthreads();
        {
            const u32 abase = sb + a_rb;
            const u32 bbase = sb + 32768u + b_rb;
            #pragma unroll
            for (int ks = 0; ks < 4; ks++) {
                const u32 aoff = (u32)(((ks * 2 + a_hi) ^ xr) << 4);
                const u32 boff = (u32)(((ks * 2 + b_hi) ^ xr) << 4);
                u32 b[4][4], a0[4], a1[4];
                #pragma unroll
                for (int p = 0; p < 4; p++)
                    ldsm4(b[p], bbase + boff + p * 2048);
                ldsm4(a0, abase + aoff);
                ldsm4(a1, abase + aoff + 2048);
                #pragma unroll
                for (int nj = 0; nj < 8; nj++) {
                    u32 bb0 = b[nj >> 1][(nj & 1) * 2], bb1 = b[nj >> 1][(nj & 1) * 2 + 1];
                    mma_f16(acc[0][nj], a0, bb0, bb1);
                    mma_f16(acc[1][nj], a1, bb0, bb1);
                }
            }
        }
        __syncthreads();
        if (pref0) load_A(gv_n, base_n, 0, 0);

        // half 1
        if (pref0) cp_wait<1>(); else cp_wait<0>();
        __syncthreads();
        {
            const u32 abase = sb + 16384u + a_rb;
            const u32 bbase = sb + 49152u + b_rb;
            #pragma unroll
            for (int ks = 0; ks < 4; ks++) {
                const u32 aoff = (u32)(((ks * 2 + a_hi) ^ xr) << 4);
                const u32 boff = (u32)(((ks * 2 + b_hi) ^ xr) << 4);
                u32 b[4][4], a0[4], a1[4];
                #pragma unroll
                for (int p = 0; p < 4; p++)
                    ldsm4(b[p], bbase + boff + p * 2048);
                ldsm4(a0, abase + aoff);
                ldsm4(a1, abase + aoff + 2048);
                #pragma unroll
                for (int nj = 0; nj < 8; nj++) {
                    u32 bb0 = b[nj >> 1][(nj & 1) * 2], bb1 = b[nj >> 1][(nj & 1) * 2 + 1];
                    mma_f16(acc[0][nj], a0, bb0, bb1);
                    mma_f16(acc[1][nj], a1, bb0, bb1);
                }
            }
        }

        // all smem reads for this tile are complete -> safe to overwrite stages
        __syncthreads();
        if (have_next) {
            if (g_n == curg) {
                load_A(gv_n, base_n, 1, 1);
            } else {
                // pref0 was false -> half-1 used cp_wait<0>, all groups drained
                load_B(Bw_n);
                load_A(gv_n, base_n, 0, 0);
                load_A(gv_n, base_n, 1, 1);
            }
        }

        // epilogue (registers + global red only) overlaps the cp.async above
        #pragma unroll
        for (int mi = 0; mi < 2; mi++) {
            int lr1 = m0w + mi * 16 + g;
            i64 dr1 = su ? (i64)__ldg(su + lr1)     : (i64)(base_row + lr1);
            i64 dr2 = su ? (i64)__ldg(su + lr1 + 8) : (i64)(base_row + lr1 + 8);
            float* pr = evenlane ? (T + dr1 * D) : (T + dr2 * D);
            #pragma unroll
            for (int nj = 0; nj < 8; nj++) {
                float v0 = acc[mi][nj][0], v1 = acc[mi][nj][1];
                float v2 = acc[mi][nj][2], v3 = acc[mi][nj][3];
                float p0 = __shfl_xor_sync(0xffffffffu, v0, 1);
                float p1 = __shfl_xor_sync(0xffffffffu, v1, 1);
                float p2 = __shfl_xor_sync(0xffffffffu, v2, 1);
                float p3 = __shfl_xor_sync(0xffffffffu, v3, 1);
                if (evenlane) red4(pr + cb + nj * 8, v0, v1, p0, p1);
                else          red4(pr + cb + nj * 8, p2, p3, v2, v3);
            }
        }

        if (have_next) {
            curg = g_n; gv = gv_n; su = su_n; base_row = base_n;
        }
    }
}

// ---------------- merged prolog kernel (cvt x11 + zero T + X=feats) --------------
#define NSEG 11
struct PrologArgs {
    const float4* src[NSEG];
    uint2* dst[NSEG];
    int n4[NSEG];
    float4* T;
    float4* X;
    const float4* feats;
    int nT4;
};
__global__ __launch_bounds__(256)
void prolog_k(PrologArgs a)
{
    const int seg = blockIdx.y;
    const int i = blockIdx.x * 256 + threadIdx.x;
    if (seg < NSEG) {
        if (i < a.n4[seg]) a.dst[seg][i] = cvt4(a.src[seg][i]);
    } else if (seg == NSEG) {
        if (i < a.nT4) a.T[i] = make_float4(0.f, 0.f, 0.f, 0.f);
    } else {
        if (i < a.nT4) a.X[i] = a.feats[i];
    }
}

__global__ __launch_bounds__(256)
void cvtX_k(const float4* __restrict__ X, uint2* __restrict__ xh)
{
    const int i = blockIdx.x * 256 + threadIdx.x;
    xh[i] = cvt4(X[i]);
}

// ---------------- softmax: warp-per-row, in-place over fp16 scores ---------------
__global__ __launch_bounds__(256)
void softmax_h(f16* __restrict__ sch)
{
    const i64 row = (i64)blockIdx.x * 8 + (threadIdx.x >> 5);
    const int lane = threadIdx.x & 31;
    f16* p = sch + row * NSEQ + lane * 32;

    float f[32];
    #pragma unroll
    for (int j = 0; j < 4; j++) {
        uint4 r = *reinterpret_cast<const uint4*>(p + j * 8);
        const u32 w[4] = {r.x, r.y, r.z, r.w};
        #pragma unroll
        for (int e = 0; e < 4; e++) {
            __half2 h = *(const __half2*)&w[e];
            float2 ff = __half22float2(h);
            f[j * 8 + e * 2]     = ff.x;
            f[j * 8 + e * 2 + 1] = ff.y;
        }
    }
    float mx = f[0];
    #pragma unroll
    for (int j = 1; j < 32; j++) mx = fmaxf(mx, f[j]);
    #pragma unroll
    for (int o = 16; o; o >>= 1) mx = fmaxf(mx, __shfl_xor_sync(0xffffffffu, mx, o));
    float s = 0.f;
    #pragma unroll
    for (int j = 0; j < 32; j++) { f[j] = __expf(f[j] - mx); s += f[j]; }
    #pragma unroll
    for (int o = 16; o; o >>= 1) s += __shfl_xor_sync(0xffffffffu, s, o);
    const float inv = 1.0f / s;
    #pragma unroll
    for (int j = 0; j < 4; j++) {
        uint4 r;
        u32* w = (u32*)&r;
        #pragma unroll
        for (int e = 0; e < 4; e++) {
            __half2 h = __floats2half2_rn(f[j * 8 + e * 2] * inv, f[j * 8 + e * 2 + 1] * inv);
            w[e] = *(u32*)&h;
        }
        *reinterpret_cast<uint4*>(p + j * 8) = r;
    }
}

// ---------------- driver ---------------------------------------------------------
#define SMEM_GN 67584
#define SMEM_QK 98304
#define SMEM_PV 65536
#define SMEM_SC 65536

extern "C" void kernel_launch(void* const* d_in, const int* in_sizes, int n_in,
                              void* d_out, int out_size)
{
    (void)in_sizes; (void)n_in; (void)out_size;
    const float* ctrs   = (const float*)d_in[0];
    const float* feats  = (const float*)d_in[1];
    const float* Wq     = (const float*)d_in[2];
    const float* Wk     = (const float*)d_in[3];
    const float* Wv     = (const float*)d_in[4];
    const float* Wc     = (const float*)d_in[5];
    const float* Wp     = (const float*)d_in[6];
    const float* Ws     = (const float*)d_in[7];
    const float* Wl     = (const float*)d_in[8];
    const float* Wr     = (const float*)d_in[9];
    const float* Wc2    = (const float*)d_in[10];
    const float* g1     = (const float*)d_in[11];
    const float* b1     = (const float*)d_in[12];
    const float* g2     = (const float*)d_in[13];
    const float* b2     = (const float*)d_in[14];
    const int* pre_u    = (const int*)d_in[15];
    const int* pre_v    = (const int*)d_in[16];
    const int* suc_u    = (const int*)d_in[17];
    const int* suc_v    = (const int*)d_in[18];
    const int* left_u   = (const int*)d_in[19];
    const int* left_v   = (const int*)d_in[20];
    const int* right_u  = (const int*)d_in[21];
    const int* right_v  = (const int*)d_in[22];
    float* X = (float*)d_out;

    float *T;
    cudaGetSymbolAddress((void**)&T,  g_T);
    f16 *ctrs_h, *feat_h, *q_h, *k_h, *vt_h, *x_h, *sc_h;
    f16 *wq_h, *wk_h, *wv_h, *wc_h, *wp_h, *ws_h, *wl_h, *wr_h, *w2_h;
    cudaGetSymbolAddress((void**)&ctrs_h, s_ctrs_h);
    cudaGetSymbolAddress((void**)&feat_h, s_feat_h);
    cudaGetSymbolAddress((void**)&q_h, s_q_h);
    cudaGetSymbolAddress((void**)&k_h, s_k_h);
    cudaGetSymbolAddress((void**)&vt_h, s_vt_h);
    cudaGetSymbolAddress((void**)&x_h, s_x_h);
    cudaGetSymbolAddress((void**)&sc_h, s_sc_h);
    cudaGetSymbolAddress((void**)&wq_h, s_wq_h);
    cudaGetSymbolAddress((void**)&wk_h, s_wk_h);
    cudaGetSymbolAddress((void**)&wv_h, s_wv_h);
    cudaGetSymbolAddress((void**)&wc_h, s_wc_h);
    cudaGetSymbolAddress((void**)&wp_h, s_wp_h);
    cudaGetSymbolAddress((void**)&ws_h, s_ws_h);
    cudaGetSymbolAddress((void**)&wl_h, s_wl_h);
    cudaGetSymbolAddress((void**)&wr_h, s_wr_h);
    cudaGetSymbolAddress((void**)&w2_h, s_w2_h);

    cudaFuncSetAttribute((const void*)gemm_gn12_k, cudaFuncAttributeMaxDynamicSharedMemorySize, SMEM_GN);
    cudaFuncSetAttribute((const void*)qkv_k, cudaFuncAttributeMaxDynamicSharedMemorySize, SMEM_GN);
    cudaFuncSetAttribute((const void*)qk_k, cudaFuncAttributeMaxDynamicSharedMemorySize, SMEM_QK);
    cudaFuncSetAttribute((const void*)pv_k, cudaFuncAttributeMaxDynamicSharedMemorySize, SMEM_PV);
    cudaFuncSetAttribute((const void*)layer_scatter_p, cudaFuncAttributeMaxDynamicSharedMemorySize, SMEM_SC);

    const float NF = 0.08838834764831845f;  // 1/sqrt(128)
    dim3 blk(256);

    // ---- single prolog launch: 11 conversions + zero T + X = feats ----
    PrologArgs pa;
    const float* srcs[NSEG] = {ctrs, feats, Wq, Wk, Wv, Wc, Wp, Ws, Wl, Wr, Wc2};
    f16* dsts[NSEG] = {ctrs_h, feat_h, wq_h, wk_h, wv_h, wc_h, wp_h, ws_h, wl_h, wr_h, w2_h};
    const int ns[NSEG] = {M_ROWS*D, M_ROWS*D, DD, DD, DD, NL*DD, NL*NS*DD, NL*NS*DD, NL*DD, NL*DD, NL*DD};
    int maxn4 = M_ROWS * D / 4;
    for (int i = 0; i < NSEG; i++) {
        pa.src[i] = (const float4*)srcs[i];
        pa.dst[i] = (uint2*)dsts[i];
        pa.n4[i] = ns[i] / 4;
        if (pa.n4[i] > maxn4) maxn4 = pa.n4[i];
    }
    pa.T = (float4*)T;
    pa.X = (float4*)X;
    pa.feats = (const float4*)feats;
    pa.nT4 = M_ROWS * D / 4;
    prolog_k<<<dim3((maxn4 + 255) / 256, NSEG + 2), 256>>>(pa);

    // ---- attention ----
    qkv_k<<<dim3(128, 1, 3), blk, SMEM_GN>>>(ctrs_h, feat_h, wq_h, wk_h, wv_h, q_h, k_h, vt_h);
    qk_k<<<dim3(8, 2, 16), blk, SMEM_QK>>>(q_h, k_h, sc_h, NF);
    softmax_h<<<M_ROWS / 8, 256>>>(sc_h);
    pv_k<<<dim3(8, 1, 32), blk, SMEM_PV>>>(sc_h, vt_h, X);
    cvtX_k<<<M_ROWS * D / 4 / 256, 256>>>((const float4*)X, (uint2*)x_h);

    // ---- 4-layer fusion loop (2 launches per layer) ----
    for (int i = 0; i < NL; i++) {
        layer_scatter_p<<<GRID_SC, blk, SMEM_SC>>>(
            x_h,
            wc_h + (i64)i*DD,
            wp_h + (i64)i*NS*DD,
            ws_h + (i64)i*NS*DD,
            wl_h + (i64)i*DD,
            wr_h + (i64)i*DD,
            T, pre_u, pre_v, suc_u, suc_v, left_u, left_v, right_u, right_v);
        gemm_gn12_k<<<dim3(128, 1, 1), blk, SMEM_GN>>>(
            T, w2_h + (i64)i*DD, X, x_h,
            g1 + i*D, b1 + i*D, g2 + i*D, b2 + i*D);
    }
}